// round 17
// baseline (speedup 1.0000x reference)
#include <cuda_runtime.h>
#include <cstdint>

// DeltaLoss, rank-96 factorization. R17: prep restructured around Gram matrices.
//  gram3 : gtt/gii/gti via 6x48 row-blocking (left rows in smem, right streamed)
//  metaw : W tiles from smem-staged gti (+ per-q si recomputed from gii);
//          meta blocks compute k1/diag/ij from Gram entries; zeroing fused.
//  lse   : unchanged R16 loop (measured floor), ticket finalize.
// SHIFT=30 fixed-shift LSE: x<=100 -> no overflow; sums stay normal fp32.

#define NN    96
#define D     512
#define P2    4560            // NN*(NN-1)/2
#define P2PAD 4608
#define PBLK  256
#define QBLK  128
#define GQ    (P2PAD / QBLK)  // 36
#define GP    (P2PAD / PBLK)  // 18
#define NBLOCKS (GQ * GP)     // 648
#define K2C   (-43.28085122666891f)   // -30*log2(e)
#define L2E100 144.26950408889634f    // 100*log2(e)

// ---- scratch ----
__device__ float g_gtt[NN * NN];
__device__ float g_gii[NN * NN];
__device__ float g_gti[NN * NN];      // [txt row][img col]
__device__ float g_W[(size_t)NN * P2PAD];
__device__ uint32_t g_ij[P2PAD];
__device__ float g_k1[P2PAD];
__device__ float g_diag[P2PAD];
__device__ float g_rowSum[P2PAD];
__device__ float g_colSum[P2PAD];
__device__ unsigned int g_done;

__device__ __forceinline__ float ex2f(float x) {
    float y;
    asm("ex2.approx.f32 %0, %1;" : "=f"(y) : "f"(x));
    return y;
}
__device__ __forceinline__ uint32_t smem_u32(const void* p) {
    uint32_t a;
    asm("{ .reg .u64 t; cvta.to.shared.u64 t, %1; cvt.u32.u64 %0, t; }" : "=r"(a) : "l"(p));
    return a;
}
__device__ __forceinline__ float warp_sum(float v) {
    #pragma unroll
    for (int o = 16; o > 0; o >>= 1) v += __shfl_xor_sync(0xffffffffu, v, o);
    return v;
}

// triangular index p -> (i, j), i<j lexicographic; off(i) = i*(191-i)/2 (NN=96)
__device__ __forceinline__ void tri_ij(int p, int& i, int& j) {
    const float disc = (2.f * NN - 1.f) * (2.f * NN - 1.f) - 8.f * (float)p;
    int ii = (int)(((2.f * NN - 1.f) - sqrtf(disc)) * 0.5f);
    ii = ii < 0 ? 0 : (ii > NN - 2 ? NN - 2 : ii);
    while (ii > 0 && p < ii * (191 - ii) / 2) --ii;
    while (p >= (ii + 1) * (190 - ii) / 2) ++ii;
    i = ii;
    j = ii + 1 + (p - ii * (191 - ii) / 2);
}

// ---- gram3: 96 blocks = 3 grams x 16 left-tiles(6 rows) x 2 right-halves(48) ----
__global__ __launch_bounds__(256) void gram_kernel(const float* __restrict__ txtf,
                                                   const float* __restrict__ imgf) {
    __shared__ float Ls[6 * D];                        // 12 KB
    const int bid = blockIdx.x;
    const int tid = threadIdx.x;
    const int g  = bid >> 5;          // 0: tt, 1: ii, 2: ti
    const int sub = bid & 31;
    const int lt = sub >> 1;          // 0..15
    const int rh = sub & 1;           // 0..1

    const float* __restrict__ lsrc = (g == 1) ? imgf : txtf;
    const float* __restrict__ rsrc = (g == 0) ? txtf : imgf;
    float* __restrict__ dst = (g == 0) ? g_gtt : ((g == 1) ? g_gii : g_gti);

    #pragma unroll
    for (int k = 0; k < 3; ++k)
        ((float4*)Ls)[tid + k * 256] =
            ((const float4*)(lsrc + lt * 6 * D))[tid + k * 256];
    __syncthreads();

    const int w = tid >> 5, lane = tid & 31;
    #pragma unroll
    for (int k = 0; k < 6; ++k) {
        const int r = rh * 48 + w * 6 + k;
        const float4* __restrict__ v = (const float4*)(rsrc + r * D);
        float4 rv0 = v[lane], rv1 = v[lane + 32], rv2 = v[lane + 64], rv3 = v[lane + 96];
        #pragma unroll
        for (int L = 0; L < 6; ++L) {
            const float4* __restrict__ ls = (const float4*)(Ls + L * D);
            const float4 a0 = ls[lane], a1 = ls[lane + 32];
            const float4 a2 = ls[lane + 64], a3 = ls[lane + 96];
            float s = 0.f;
            s = fmaf(a0.x, rv0.x, s); s = fmaf(a0.y, rv0.y, s);
            s = fmaf(a0.z, rv0.z, s); s = fmaf(a0.w, rv0.w, s);
            s = fmaf(a1.x, rv1.x, s); s = fmaf(a1.y, rv1.y, s);
            s = fmaf(a1.z, rv1.z, s); s = fmaf(a1.w, rv1.w, s);
            s = fmaf(a2.x, rv2.x, s); s = fmaf(a2.y, rv2.y, s);
            s = fmaf(a2.z, rv2.z, s); s = fmaf(a2.w, rv2.w, s);
            s = fmaf(a3.x, rv3.x, s); s = fmaf(a3.y, rv3.y, s);
            s = fmaf(a3.z, rv3.z, s); s = fmaf(a3.w, rv3.w, s);
            s = warp_sum(s);
            if (lane == 0) dst[(lt * 6 + L) * NN + r] = s;
        }
    }
}

// ---- metaw: blocks 0..17 build W tiles from smem gti; 18..35 do pair meta ----
__global__ __launch_bounds__(256) void metaw_kernel() {
    __shared__ float gti_s[NN * NN];                   // 36 KB
    const int bid = blockIdx.x;
    const int tid = threadIdx.x;

    if (bid < 18) {
        // stage full gti (9216 floats = 2304 float4)
        #pragma unroll
        for (int k = 0; k < 9; ++k)
            ((float4*)gti_s)[tid + k * 256] = ((const float4*)g_gti)[tid + k * 256];
        __syncthreads();

        const int q = bid * 256 + tid;
        int i = 0, j = 1;
        float si = 0.f;
        if (q < P2) {
            tri_ij(q, i, j);
            const float nii = g_gii[i * NN + i] - 2.f * g_gii[i * NN + j]
                            + g_gii[j * NN + j];
            si = 1.f / (sqrtf(nii) + 1e-8f);
        }
        #pragma unroll 4
        for (int r = 0; r < NN; ++r)
            g_W[(size_t)r * P2PAD + q] = si * (gti_s[r * NN + i] - gti_s[r * NN + j]);
        return;
    }

    // meta blocks: k1, diag, ij, zeroing
    const int p = (bid - 18) * 256 + tid;
    g_rowSum[p] = 0.f;
    g_colSum[p] = 0.f;
    if (p == 0) g_done = 0u;
    if (p >= P2) { g_ij[p] = 0u; g_k1[p] = 0.f; g_diag[p] = 0.f; return; }

    int i, j;
    tri_ij(p, i, j);
    const float ntt = g_gtt[i * NN + i] - 2.f * g_gtt[i * NN + j] + g_gtt[j * NN + j];
    const float nii = g_gii[i * NN + i] - 2.f * g_gii[i * NN + j] + g_gii[j * NN + j];
    const float dd  = g_gti[i * NN + i] - g_gti[i * NN + j]
                    - g_gti[j * NN + i] + g_gti[j * NN + j];
    const float st = 1.f / (sqrtf(ntt) + 1e-8f);
    const float si = 1.f / (sqrtf(nii) + 1e-8f);
    g_ij[p] = (uint32_t)i | ((uint32_t)j << 8);
    g_k1[p] = L2E100 * st;
    g_diag[p] = 100.f * st * si * dd;
}

// one group of 4 p (lanes own 4 q via LDS.128): entries, butterfly rows, col acc
template <bool MASKED>
__device__ __forceinline__ void lse_group(
    int g, int pbase, int p0, int lane, uint32_t wbase,
    const float2* __restrict__ ksm, const uint32_t* __restrict__ offsm,
    float mq0, float mq1, float mq2, float mq3,
    float& c0, float& c1, float& c2, float& c3)
{
    float rsv[4];
    #pragma unroll
    for (int u = 0; u < 4; ++u) {
        const int p = pbase + g * 4 + u;
        const uint32_t off = offsm[p];
        const float2 kb = ksm[p];
        float4 vi, vj;
        asm volatile("ld.shared.v4.f32 {%0,%1,%2,%3}, [%4];"
            : "=f"(vi.x), "=f"(vi.y), "=f"(vi.z), "=f"(vi.w)
            : "r"(wbase + (off & 0xFFFFu)));
        asm volatile("ld.shared.v4.f32 {%0,%1,%2,%3}, [%4];"
            : "=f"(vj.x), "=f"(vj.y), "=f"(vj.z), "=f"(vj.w)
            : "r"(wbase + (off >> 16)));
        const float d0 = vi.x - vj.x, d1 = vi.y - vj.y;
        const float d2 = vi.z - vj.z, d3 = vi.w - vj.w;
        const float e0 = ex2f(fmaf(d0, kb.x, kb.y)) + ex2f(fmaf(d0, -kb.x, kb.y));
        const float e1 = ex2f(fmaf(d1, kb.x, kb.y)) + ex2f(fmaf(d1, -kb.x, kb.y));
        const float e2 = ex2f(fmaf(d2, kb.x, kb.y)) + ex2f(fmaf(d2, -kb.x, kb.y));
        const float e3 = ex2f(fmaf(d3, kb.x, kb.y)) + ex2f(fmaf(d3, -kb.x, kb.y));
        c0 += e0; c1 += e1; c2 += e2; c3 += e3;
        if constexpr (MASKED) {
            float rs = e0 * mq0;
            rs = fmaf(e1, mq1, rs);
            rs = fmaf(e2, mq2, rs);
            rs = fmaf(e3, mq3, rs);
            rsv[u] = rs;
        } else {
            rsv[u] = (e0 + e1) + (e2 + e3);
        }
    }
    float v0 = rsv[0] + __shfl_xor_sync(0xffffffffu, rsv[0], 16);
    float t1 = rsv[1] + __shfl_xor_sync(0xffffffffu, rsv[1], 16);
    v0 = (lane & 16) ? t1 : v0;
    float v1 = rsv[2] + __shfl_xor_sync(0xffffffffu, rsv[2], 16);
    float t3 = rsv[3] + __shfl_xor_sync(0xffffffffu, rsv[3], 16);
    v1 = (lane & 16) ? t3 : v1;
    float u0 = v0 + __shfl_xor_sync(0xffffffffu, v0, 8);
    float u1 = v1 + __shfl_xor_sync(0xffffffffu, v1, 8);
    u0 = (lane & 8) ? u1 : u0;
    u0 += __shfl_xor_sync(0xffffffffu, u0, 4);
    u0 += __shfl_xor_sync(0xffffffffu, u0, 2);
    u0 += __shfl_xor_sync(0xffffffffu, u0, 1);
    if ((lane & 7) == 0) {
        const int idx = ((lane >> 4) & 1) | ((lane >> 2) & 2);
        atomicAdd(&g_rowSum[p0 + pbase + g * 4 + idx], u0);
    }
}

// ---- lse: W tile loaded coalesced from g_W, 256p x 128q, ticket finalize ----
__global__ void __launch_bounds__(256) lse_main(float* __restrict__ out) {
    __shared__ float Wsm[NN * QBLK];                   // 49152 B
    __shared__ float2 ksm[PBLK];
    __shared__ uint32_t offsm[PBLK];
    __shared__ float red[8];
    __shared__ unsigned int s_last;

    const int tid = threadIdx.x;
    const int q0 = blockIdx.x * QBLK;
    const int p0 = blockIdx.y * PBLK;

    #pragma unroll
    for (int k = 0; k < 12; ++k) {
        const int f4 = tid + k * 256;
        const int r = f4 >> 5, c = f4 & 31;
        ((float4*)Wsm)[f4] = *(const float4*)(g_W + (size_t)r * P2PAD + q0 + c * 4);
    }
    {
        const int p = p0 + tid;
        ksm[tid] = make_float2(g_k1[p], (p < P2) ? K2C : -2000.f);
        const uint32_t pij = g_ij[p];
        offsm[tid] = ((pij & 255u) * (QBLK * 4)) | (((pij >> 8) * (QBLK * 4)) << 16);
    }
    __syncthreads();

    const int w = tid >> 5, lane = tid & 31;
    const uint32_t wbase = smem_u32(Wsm) + (uint32_t)lane * 16u;
    const int pbase = w * 32;
    float c0 = 0.f, c1 = 0.f, c2 = 0.f, c3 = 0.f;
    const int gq = q0 + 4 * lane;

    if (q0 + QBLK <= P2) {
        #pragma unroll 2
        for (int g = 0; g < 8; ++g)
            lse_group<false>(g, pbase, p0, lane, wbase, ksm, offsm,
                             1.f, 1.f, 1.f, 1.f, c0, c1, c2, c3);
    } else {
        const float mq0 = (gq + 0 < P2) ? 1.f : 0.f;
        const float mq1 = (gq + 1 < P2) ? 1.f : 0.f;
        const float mq2 = (gq + 2 < P2) ? 1.f : 0.f;
        const float mq3 = (gq + 3 < P2) ? 1.f : 0.f;
        #pragma unroll 2
        for (int g = 0; g < 8; ++g)
            lse_group<true>(g, pbase, p0, lane, wbase, ksm, offsm,
                            mq0, mq1, mq2, mq3, c0, c1, c2, c3);
    }

    atomicAdd(&g_colSum[gq + 0], c0);
    atomicAdd(&g_colSum[gq + 1], c1);
    atomicAdd(&g_colSum[gq + 2], c2);
    atomicAdd(&g_colSum[gq + 3], c3);

    __syncthreads();
    if (tid == 0) {
        __threadfence();
        s_last = (atomicAdd(&g_done, 1u) == (unsigned)(NBLOCKS - 1)) ? 1u : 0u;
    }
    __syncthreads();
    if (s_last) {
        __threadfence();
        float s = 0.f;
        for (int p = tid; p < P2; p += 256)
            s += 30.0f + 0.5f * (logf(g_rowSum[p]) + logf(g_colSum[p])) - g_diag[p];
        s = warp_sum(s);
        if ((tid & 31) == 0) red[tid >> 5] = s;
        __syncthreads();
        if (tid == 0) {
            float tot = 0.f;
            #pragma unroll
            for (int k = 0; k < 8; ++k) tot += red[k];
            out[0] = tot / (float)P2;
        }
    }
}

extern "C" void kernel_launch(void* const* d_in, const int* in_sizes, int n_in,
                              void* d_out, int out_size) {
    const float* txtf = (const float*)d_in[0];
    const float* imgf = (const float*)d_in[1];
    (void)in_sizes; (void)n_in; (void)out_size;
    float* out = (float*)d_out;

    gram_kernel<<<96, 256>>>(txtf, imgf);
    metaw_kernel<<<36, 256>>>();
    lse_main<<<dim3(GQ, GP), 256>>>(out);
}